// round 8
// baseline (speedup 1.0000x reference)
#include <cuda_runtime.h>
#include <math.h>

#define BB 16
#define TT 50
#define NGT (BB*TT)                 // 800
#define AA 3
#define HH 76
#define WW 76
#define HWX 5776
#define NCELL 277248                // BB*AA*HWX
#define NCLS 80
#define ATTR 85
#define PRED_B (255*HWX)
#define IGNORE_THR 0.5f

#define NBITW ((NCELL + 31) / 32)   // 8664
#define TBL 1024
#define TBLM (TBL - 1)
#define MAXIGN 2432                 // >= 16*3*50 worst case

#define NV (NCELL/4)                // 69312 float4s of conf channel
#define DENSEB ((NV + 255)/256)     // 271
#define MASKB ((NGT + 7)/8)         // 100 blocks x 8 warps
#define NBLK (1 + MASKB + DENSEB)   // 372  (block0 = encode)

__device__ __constant__ float c_aw[3] = {14.5f, 19.5f, 46.625f};
__device__ __constant__ float c_ah[3] = {11.25f, 24.75f, 40.75f};

// ---------------- global scratch (no per-run reset needed except noted) -----
__device__ unsigned int g_ignw[NBITW];       // dedupe bitmap (encode clears)
__device__ int          g_ilist[MAXIGN];
__device__ int          g_icnt;              // encode resets
__device__ int          g_rcell[NGT];
__device__ float        g_rtx[NGT], g_rty[NGT], g_rtw[NGT], g_rth[NGT];
__device__ unsigned int g_rtcls[NGT*3];
__device__ int          g_npos;
__device__ double       g_p0[NBLK], g_p1[NBLK], g_p2[NBLK];  // partial slots
__device__ unsigned int g_done;              // finalizer resets
__device__ volatile unsigned int g_flag;     // finalizer resets

// fast softplus: log(1+e^z); logits bounded ~|5.6| so approx intrinsics safe
__device__ __forceinline__ float spf(float z) {
    return __logf(1.0f + __expf(z));
}

// block-reduce one double, result valid at thread 0
__device__ __forceinline__ double blk_red(double v, double* sh) {
    #pragma unroll
    for (int o = 16; o; o >>= 1) v += __shfl_down_sync(0xffffffffu, v, o);
    int lane = threadIdx.x & 31, wid = threadIdx.x >> 5;
    if (lane == 0) sh[wid] = v;
    __syncthreads();
    double t = 0.0;
    if (threadIdx.x == 0) {
        #pragma unroll
        for (int w = 0; w < 8; ++w) t += sh[w];
    }
    __syncthreads();
    return t;
}

__global__ void __launch_bounds__(256, 3)
k_fused(const float* __restrict__ pred, const float* __restrict__ annot,
        float* __restrict__ out, int out_n) {
    __shared__ int          s_key[TBL];
    __shared__ int          s_prio[TBL];
    __shared__ unsigned int s_cls[TBL*3];
    __shared__ short        s_rec[TBL];
    __shared__ int          s_cnt;
    __shared__ double       s_red[8];
    __shared__ int          s_last;

    const int tid = threadIdx.x;
    const int bid = blockIdx.x;
    double c0 = 0.0, c1 = 0.0, c2 = 0.0;   // this block's partial contributions

    if (bid == 0) {
        // ================= ENCODE BLOCK =================
        for (int i = tid; i < TBL; i += 256) {
            s_key[i] = -1; s_prio[i] = -1;
            s_cls[i*3] = 0u; s_cls[i*3+1] = 0u; s_cls[i*3+2] = 0u;
        }
        for (int i = tid; i < NBITW; i += 256) g_ignw[i] = 0u;
        if (tid == 0) { s_cnt = 0; g_icnt = 0; }
        __syncthreads();

        // insert phase: up to 4 GTs per thread (JAX negative-index WRAP semantics)
        int   slot[4], myt[4];
        float vtx[4], vty[4], vtw[4], vth[4];
        #pragma unroll
        for (int it = 0; it < 4; ++it) {
            slot[it] = -1;
            int g = tid + it * 256;
            if (g >= NGT) continue;
            int b = g / TT, t = g - b * TT;
            const float* an = annot + g * 5;
            float a0 = an[0], a1 = an[1], a2 = an[2], a3 = an[3], a4 = an[4];
            bool valid = (a0 + a1 + a2 + a3 + a4) != 0.0f;

            float gx = a1 * (float)WW, gy = a2 * (float)HH;
            float gw = a3 * (float)WW, gh = a4 * (float)HH;
            int gi = (int)floorf(gx), gj = (int)floorf(gy);

            float ious[3];
            float best = -1.0f; int bn = 0;
            const float eps = 1e-9f;
            #pragma unroll
            for (int a = 0; a < 3; ++a) {
                float inter = fminf(gw, c_aw[a]) * fminf(gh, c_ah[a]);
                float un = gw * (gh + eps) + c_aw[a] * (c_ah[a] + eps) - inter + eps;
                float iou = inter / un;
                ious[a] = iou;
                if (iou > best) { best = iou; bn = a; }      // first max
            }

            if (gi >= 0 && gi < WW && gj >= 0 && gj < HH) {
                // ignore cells: failing anchors WRAP to anchor 2
                #pragma unroll
                for (int a = 0; a < 3; ++a) {
                    bool cond = (ious[a] > IGNORE_THR) && valid;
                    int ae = cond ? a : (AA - 1);
                    int c = ((b * AA + ae) * HH + gj) * WW + gi;
                    unsigned int m = 1u << (c & 31);
                    unsigned int old = atomicOr(&g_ignw[c >> 5], m);
                    if (!(old & m)) {
                        int k = atomicAdd(&g_icnt, 1);
                        g_ilist[k] = c;
                    }
                }
            }
            // mask record: invalid gi WRAPS to WW-1
            int ii = valid ? gi : (WW - 1);
            if (ii >= 0 && ii < WW && gj >= 0 && gj < HH) {
                int cell = ((b * AA + bn) * HH + gj) * WW + ii;
                int j = (int)(((unsigned int)cell * 2654435761u) >> 22) & TBLM;
                while (true) {
                    int old = atomicCAS(&s_key[j], -1, cell);
                    if (old == -1) {
                        int r = atomicAdd(&s_cnt, 1);
                        s_rec[j] = (short)r;
                        g_rcell[r] = cell;
                        break;
                    }
                    if (old == cell) break;
                    j = (j + 1) & TBLM;
                }
                atomicMax(&s_prio[j], t);                    // XLA last-wins
                int ci = (int)a0;
                if (ci >= 0 && ci < NCLS)
                    atomicOr(&s_cls[j*3 + (ci >> 5)], 1u << (ci & 31));
                slot[it] = j; myt[it] = t;
                vtx[it] = gx - (float)gi;
                vty[it] = gy - (float)gj;
                vtw[it] = __logf(gw / c_aw[bn] + 1e-16f);
                vth[it] = __logf(gh / c_ah[bn] + 1e-16f);
            }
        }
        __syncthreads();

        // unique winner writes its record
        #pragma unroll
        for (int it = 0; it < 4; ++it) {
            if (slot[it] >= 0 && s_prio[slot[it]] == myt[it]) {
                int r = (int)s_rec[slot[it]];
                g_rtx[r] = vtx[it]; g_rty[r] = vty[it];
                g_rtw[r] = vtw[it]; g_rth[r] = vth[it];
                g_rtcls[r*3+0] = s_cls[slot[it]*3+0];
                g_rtcls[r*3+1] = s_cls[slot[it]*3+1];
                g_rtcls[r*3+2] = s_cls[slot[it]*3+2];
            }
        }
        if (tid == 0) g_npos = s_cnt;
        __syncthreads();
        __threadfence();
        if (tid == 0) g_flag = 1u;                           // release to mask blocks

        // subtract ignored cells from dense conf sum
        int icnt = g_icnt;
        double s = 0.0;
        for (int k = tid; k < icnt; k += 256) {
            int cell = g_ilist[k];
            int pix = cell % HWX;
            int ra = cell / HWX;
            int b = ra / AA, a = ra - b * AA;
            s -= (double)spf(pred[(size_t)b * PRED_B + (size_t)(a * ATTR + 4) * HWX + pix]);
        }
        c0 = s;
    } else if (bid <= MASKB) {
        // ================= MASK BLOCKS (spin until encode done) ==========
        if (tid == 0) {
            while (g_flag == 0u) __nanosleep(64);
        }
        __syncthreads();
        __threadfence();                                     // acquire

        int widx = (bid - 1) * 8 + (tid >> 5);
        int lane = tid & 31;
        double lcls = 0.0, lobj = 0.0;
        if (widx < g_npos) {
            int cell = g_rcell[widx];
            int pix = cell % HWX;
            int ra = cell / HWX;
            int b = ra / AA, a = ra - b * AA;
            const float* base = pred + (size_t)b * PRED_B + (size_t)(a * ATTR) * HWX;

            #pragma unroll
            for (int q = 0; q < 3; ++q) {
                int cc = lane + 32 * q;
                if (cc < NCLS) {
                    float z = base[(size_t)(5 + cc) * HWX + pix];
                    bool tgt = (g_rtcls[widx*3 + q] >> lane) & 1u;
                    lcls += (double)(tgt ? spf(-z) : spf(z));
                }
            }
            if (lane == 0) {
                float zx = base[(size_t)0 * HWX + pix];
                float zy = base[(size_t)1 * HWX + pix];
                float zw = base[(size_t)2 * HWX + pix];
                float zh = base[(size_t)3 * HWX + pix];
                float zc = base[(size_t)4 * HWX + pix];
                float tx = g_rtx[widx], ty = g_rty[widx];
                float tw = g_rtw[widx], th = g_rth[widx];
                double lxy = (double)(tx * spf(-zx) + (1.0f - tx) * spf(zx))
                           + (double)(ty * spf(-zy) + (1.0f - ty) * spf(zy));
                double lwh = (double)((zw - tw) * (zw - tw) + (zh - th) * (zh - th));
                lobj = 0.5 * lxy + 2.5 * lwh + (double)spf(-zc);
            }
        }
        c1 = lobj; c2 = lcls;
    } else {
        // ================= DENSE BLOCKS (unconditional conf sum) =========
        int t4 = (bid - 1 - MASKB) * 256 + tid;
        if (t4 < NV) {
            const int V_ROW = HWX / 4;                       // 1444
            int r = t4 / V_ROW;
            int v = t4 - r * V_ROW;
            int b = r / AA, a = r - b * AA;
            const float4 f = *reinterpret_cast<const float4*>(
                pred + (size_t)b * PRED_B + (size_t)(a * ATTR + 4) * HWX + 4 * v);
            // log of product: 4 exp + 1 log instead of 4 exp + 4 log
            float p = (1.0f + __expf(f.x)) * (1.0f + __expf(f.y))
                    * (1.0f + __expf(f.z)) * (1.0f + __expf(f.w));
            c0 = (double)__logf(p);
        }
    }

    // ================= common epilogue: partial slots + last-block finalize ==
    c0 = blk_red(c0, s_red);
    c1 = blk_red(c1, s_red);
    c2 = blk_red(c2, s_red);
    if (tid == 0) {
        g_p0[bid] = c0; g_p1[bid] = c1; g_p2[bid] = c2;
        __threadfence();
        unsigned int prev = atomicAdd(&g_done, 1u);
        s_last = (prev == (unsigned int)(NBLK - 1)) ? 1 : 0;
    }
    __syncthreads();
    if (s_last) {
        __threadfence();
        double t0 = 0.0, t1 = 0.0, t2 = 0.0;
        for (int i = tid; i < NBLK; i += 256) {
            t0 += g_p0[i]; t1 += g_p1[i]; t2 += g_p2[i];
        }
        t0 = blk_red(t0, s_red);
        t1 = blk_red(t1, s_red);
        t2 = blk_red(t2, s_red);
        if (tid == 0) {
            double loss = (0.5 * t0 + t1) / (double)NCELL
                        + t2 / ((double)g_npos * (double)NCLS);
            float v = (float)loss;
            for (int i = 0; i < out_n; ++i) out[i] = v;
            g_done = 0u;            // reset for next graph replay
            g_flag = 0u;
        }
    }
}

extern "C" void kernel_launch(void* const* d_in, const int* in_sizes, int n_in,
                              void* d_out, int out_size) {
    const float* pred;
    const float* annot;
    if (n_in >= 2 && in_sizes[1] > in_sizes[0]) {
        pred  = (const float*)d_in[1];
        annot = (const float*)d_in[0];
    } else {
        pred  = (const float*)d_in[0];
        annot = (const float*)d_in[1];
    }
    k_fused<<<NBLK, 256>>>(pred, annot, (float*)d_out, out_size);
}

// round 9
// speedup vs baseline: 1.4435x; 1.4435x over previous
#include <cuda_runtime.h>
#include <math.h>

#define BB 16
#define TT 50
#define NGT (BB*TT)                 // 800
#define AA 3
#define HH 76
#define WW 76
#define HWX 5776
#define NCELL 277248                // BB*AA*HWX
#define NCLS 80
#define ATTR 85
#define PRED_B (255*HWX)
#define IGNORE_THR 0.5f

#define NBITW ((NCELL + 31) / 32)   // 8664
#define TBL 2048
#define TBLM (TBL - 1)

#define NV (NCELL/4)                          // 69312 float4s of conf channel
#define DENSEB ((NV + 511)/512)               // 136 blocks, 2 float4/thread
#define MASKB ((NGT + 7)/8)                   // 100 blocks x 8 warps
#define NBLK (DENSEB + MASKB)                 // 236

__device__ __constant__ float c_aw[3] = {14.5f, 19.5f, 46.625f};
__device__ __constant__ float c_ah[3] = {11.25f, 24.75f, 40.75f};

// ---------------- global scratch ----------------
__device__ unsigned int g_ign[NBITW];        // ignore bitmap (encode clears+fills)
__device__ int          g_rcell[TBL];
__device__ float        g_rtx[TBL], g_rty[TBL], g_rtw[TBL], g_rth[TBL];
__device__ unsigned int g_rtcls[TBL*3];
__device__ int          g_npos;
__device__ double       g_p0[NBLK], g_p1[NBLK], g_p2[NBLK];  // partial slots (overwritten)
__device__ unsigned int g_done;              // finalizer self-resets

// fast softplus: log(1+e^z); |z| <= ~6 here so intrinsics are safe
__device__ __forceinline__ float spf(float z) {
    return __logf(1.0f + __expf(z));
}

// block-reduce one double; valid at thread 0
__device__ __forceinline__ double blk_red(double v, double* sh) {
    #pragma unroll
    for (int o = 16; o; o >>= 1) v += __shfl_down_sync(0xffffffffu, v, o);
    int lane = threadIdx.x & 31, wid = threadIdx.x >> 5;
    if (lane == 0) sh[wid] = v;
    __syncthreads();
    double t = 0.0;
    if (threadIdx.x == 0) {
        #pragma unroll
        for (int w = 0; w < 8; ++w) t += sh[w];
    }
    __syncthreads();
    return t;
}

// ---------------- kernel 1: parallel target encode (1 block, 800 threads) ---
// One thread per (b,t). JAX negative-index WRAP semantics:
//  * padded rows -> mask cell (b, 0, 0, WW-1), tx=ty=0, tw=th=log(1e-16), cls 0
//  * noobj scatter: anchors failing iou>thr (or invalid) wrap to anchor 2
__global__ void k_encode(const float* __restrict__ annot) {
    __shared__ int          s_key[TBL];
    __shared__ int          s_prio[TBL];
    __shared__ unsigned int s_cls[TBL*3];
    __shared__ int          s_rec[TBL];
    __shared__ int          s_cnt;

    int tid = threadIdx.x;
    for (int i = tid; i < TBL; i += blockDim.x) {
        s_key[i] = -1; s_prio[i] = -1;
        s_cls[i*3] = 0u; s_cls[i*3+1] = 0u; s_cls[i*3+2] = 0u;
    }
    for (int i = tid; i < NBITW; i += blockDim.x) g_ign[i] = 0u;
    if (tid == 0) s_cnt = 0;
    __syncthreads();

    int slot = -1, myt = -1;
    float vtx = 0.f, vty = 0.f, vtw = 0.f, vth = 0.f;

    if (tid < NGT) {
        int b = tid / TT, t = tid - b * TT;
        const float* an = annot + tid * 5;
        float a0 = an[0], a1 = an[1], a2 = an[2], a3 = an[3], a4 = an[4];
        bool valid = (a0 + a1 + a2 + a3 + a4) != 0.0f;

        float gx = a1 * (float)WW, gy = a2 * (float)HH;
        float gw = a3 * (float)WW, gh = a4 * (float)HH;
        int gi = (int)floorf(gx), gj = (int)floorf(gy);

        float ious[3];
        float best = -1.0f; int bn = 0;
        const float eps = 1e-9f;
        #pragma unroll
        for (int a = 0; a < 3; ++a) {
            float inter = fminf(gw, c_aw[a]) * fminf(gh, c_ah[a]);
            float un = gw * (gh + eps) + c_aw[a] * (c_ah[a] + eps) - inter + eps;
            float iou = inter / un;
            ious[a] = iou;
            if (iou > best) { best = iou; bn = a; }   // first max
        }

        if (gi >= 0 && gi < WW && gj >= 0 && gj < HH) {
            #pragma unroll
            for (int a = 0; a < 3; ++a) {
                bool cond = (ious[a] > IGNORE_THR) && valid;
                int ae = cond ? a : (AA - 1);         // wrap to anchor 2
                int c = ((b * AA + ae) * HH + gj) * WW + gi;
                atomicOr(&g_ign[c >> 5], 1u << (c & 31));
            }
        }

        int ii = valid ? gi : (WW - 1);               // wrap to WW-1
        if (ii >= 0 && ii < WW && gj >= 0 && gj < HH) {
            int cell = ((b * AA + bn) * HH + gj) * WW + ii;
            int j = (int)(((unsigned int)cell * 2654435761u) >> 21) & TBLM;
            while (true) {
                int old = atomicCAS(&s_key[j], -1, cell);
                if (old == -1) {
                    int r = atomicAdd(&s_cnt, 1);
                    s_rec[j] = r;
                    g_rcell[r] = cell;
                    break;
                }
                if (old == cell) break;
                j = (j + 1) & TBLM;
            }
            atomicMax(&s_prio[j], t);                 // XLA last-wins
            int ci = (int)a0;
            if (ci >= 0 && ci < NCLS)
                atomicOr(&s_cls[j*3 + (ci >> 5)], 1u << (ci & 31));
            slot = j; myt = t;
            vtx = gx - (float)gi;
            vty = gy - (float)gj;
            vtw = __logf(gw / c_aw[bn] + 1e-16f);
            vth = __logf(gh / c_ah[bn] + 1e-16f);
        }
    }
    __syncthreads();

    if (slot >= 0 && s_prio[slot] == myt) {           // unique winner writes
        int r = s_rec[slot];
        g_rtx[r] = vtx; g_rty[r] = vty; g_rtw[r] = vtw; g_rth[r] = vth;
        g_rtcls[r*3+0] = s_cls[slot*3+0];
        g_rtcls[r*3+1] = s_cls[slot*3+1];
        g_rtcls[r*3+2] = s_cls[slot*3+2];
    }
    if (tid == 0) g_npos = s_cnt;
}

// ---------------- kernel 2: reduce + fused finalize --------------------------
__global__ void __launch_bounds__(256)
k_main(const float* __restrict__ pred, float* __restrict__ out, int out_n) {
    __shared__ double s_red[8];
    __shared__ int s_last;

    const int tid = threadIdx.x;
    const int bid = blockIdx.x;
    double c0 = 0.0, c1 = 0.0, c2 = 0.0;

    if (bid < DENSEB) {
        // dense: sum spf(conf) over non-ignored cells; product-log trick
        const int V_ROW = HWX / 4;                    // 1444
        float prod = 1.0f;
        #pragma unroll
        for (int g = 0; g < 2; ++g) {
            int t4 = bid * 512 + g * 256 + tid;
            if (t4 < NV) {
                int r = t4 / V_ROW;
                int v = t4 - r * V_ROW;
                int b = r / AA, a = r - b * AA;
                const float4 f = *reinterpret_cast<const float4*>(
                    pred + (size_t)b * PRED_B + (size_t)(a * ATTR + 4) * HWX + 4 * v);
                int cbase = r * HWX + 4 * v;
                unsigned int bits = g_ign[cbase >> 5] >> (cbase & 31);
                prod *= (bits & 1u) ? 1.0f : (1.0f + __expf(f.x));
                prod *= (bits & 2u) ? 1.0f : (1.0f + __expf(f.y));
                prod *= (bits & 4u) ? 1.0f : (1.0f + __expf(f.z));
                prod *= (bits & 8u) ? 1.0f : (1.0f + __expf(f.w));
            }
        }
        c0 = (double)__logf(prod);
    } else {
        // one warp per mask record
        int widx = (bid - DENSEB) * 8 + (tid >> 5);
        int lane = tid & 31;
        if (widx < g_npos) {
            int cell = g_rcell[widx];
            int pix = cell % HWX;
            int ra = cell / HWX;
            int b = ra / AA, a = ra - b * AA;
            const float* base = pred + (size_t)b * PRED_B + (size_t)(a * ATTR) * HWX;

            #pragma unroll
            for (int q = 0; q < 3; ++q) {
                int cc = lane + 32 * q;
                if (cc < NCLS) {
                    float z = base[(size_t)(5 + cc) * HWX + pix];
                    bool tgt = (g_rtcls[widx*3 + q] >> lane) & 1u;
                    c2 += (double)(tgt ? spf(-z) : spf(z));
                }
            }
            if (lane == 0) {
                float zx = base[(size_t)0 * HWX + pix];
                float zy = base[(size_t)1 * HWX + pix];
                float zw = base[(size_t)2 * HWX + pix];
                float zh = base[(size_t)3 * HWX + pix];
                float zc = base[(size_t)4 * HWX + pix];
                float tx = g_rtx[widx], ty = g_rty[widx];
                float tw = g_rtw[widx], th = g_rth[widx];
                double lxy = (double)(tx * spf(-zx) + (1.0f - tx) * spf(zx))
                           + (double)(ty * spf(-zy) + (1.0f - ty) * spf(zy));
                double lwh = (double)((zw - tw) * (zw - tw) + (zh - th) * (zh - th));
                c1 = 0.5 * lxy + 2.5 * lwh + (double)spf(-zc);
            }
        }
    }

    // partial slots + last-block finalize (slots overwritten every replay)
    c0 = blk_red(c0, s_red);
    c1 = blk_red(c1, s_red);
    c2 = blk_red(c2, s_red);
    if (tid == 0) {
        g_p0[bid] = c0; g_p1[bid] = c1; g_p2[bid] = c2;
        __threadfence();
        unsigned int prev = atomicAdd(&g_done, 1u);
        s_last = (prev == (unsigned int)(NBLK - 1)) ? 1 : 0;
    }
    __syncthreads();
    if (s_last) {
        __threadfence();
        double t0 = 0.0, t1 = 0.0, t2 = 0.0;
        for (int i = tid; i < NBLK; i += 256) {
            t0 += g_p0[i]; t1 += g_p1[i]; t2 += g_p2[i];
        }
        t0 = blk_red(t0, s_red);
        t1 = blk_red(t1, s_red);
        t2 = blk_red(t2, s_red);
        if (tid == 0) {
            double loss = (0.5 * t0 + t1) / (double)NCELL
                        + t2 / ((double)g_npos * (double)NCLS);
            float v = (float)loss;
            for (int i = 0; i < out_n; ++i) out[i] = v;
            g_done = 0u;                              // replay-safe reset
        }
    }
}

extern "C" void kernel_launch(void* const* d_in, const int* in_sizes, int n_in,
                              void* d_out, int out_size) {
    const float* pred;
    const float* annot;
    if (n_in >= 2 && in_sizes[1] > in_sizes[0]) {
        pred  = (const float*)d_in[1];
        annot = (const float*)d_in[0];
    } else {
        pred  = (const float*)d_in[0];
        annot = (const float*)d_in[1];
    }
    k_encode<<<1, NGT>>>(annot);
    k_main<<<NBLK, 256>>>(pred, (float*)d_out, out_size);
}

// round 10
// speedup vs baseline: 1.7703x; 1.2264x over previous
#include <cuda_runtime.h>
#include <math.h>

#define BB 16
#define TT 50
#define NGT (BB*TT)                 // 800
#define AA 3
#define HH 76
#define WW 76
#define HWX 5776
#define NCELL 277248                // BB*AA*HWX
#define NCLS 80
#define ATTR 85
#define PRED_B (255*HWX)
#define IGNORE_THR 0.5f

#define NBITW ((NCELL + 31) / 32)   // 8664
#define TBL 2048
#define TBLM (TBL - 1)

#define NV (NCELL/4)                          // 69312 float4s of conf
#define DENSE_BLOCKS ((NV + 255)/256)         // 271
#define MASK_BLOCKS ((NGT + 7)/8)             // 100 blocks x 8 warps
#define TOTAL_BLOCKS (DENSE_BLOCKS + MASK_BLOCKS)   // 371

__device__ __constant__ float c_aw[3] = {14.5f, 19.5f, 46.625f};
__device__ __constant__ float c_ah[3] = {11.25f, 24.75f, 40.75f};

// ---------------- global scratch ----------------
__device__ unsigned int g_ign[NBITW];        // noobj-ignore bitmap
__device__ int          g_rcell[TBL];
__device__ float        g_rtx[TBL], g_rty[TBL], g_rtw[TBL], g_rth[TBL];
__device__ unsigned int g_rtcls[TBL*3];
__device__ int          g_npos;
__device__ double       g_acc[3];            // 0: conf-noobj, 1: obj terms, 2: cls
__device__ unsigned int g_done;

// fast softplus: log(1+e^z); |z| <= ~6 here so approx intrinsics are safe
__device__ __forceinline__ float spf(float z) {
    return __logf(1.0f + __expf(z));
}

__device__ __forceinline__ void blk_atomic(double v, double* dst) {
    #pragma unroll
    for (int o = 16; o; o >>= 1) v += __shfl_down_sync(0xffffffffu, v, o);
    __shared__ double sh[8];
    int lane = threadIdx.x & 31, wid = threadIdx.x >> 5;
    if (lane == 0) sh[wid] = v;
    __syncthreads();
    if (threadIdx.x == 0) {
        double t = 0.0;
        #pragma unroll
        for (int w = 0; w < 8; ++w) t += sh[w];
        if (t != 0.0) atomicAdd(dst, t);
    }
}

// ---------------- kernel 1: parallel target encode (1 block, 800 threads) ---
// One thread per (b,t). JAX negative-index WRAP semantics:
//  * padded rows -> mask cell (b, 0, 0, WW-1), tx=ty=0, tw=th=log(1e-16), cls 0
//  * noobj scatter: anchors failing iou>thr (or invalid) wrap to anchor 2
__global__ void k_encode(const float* __restrict__ annot) {
    __shared__ int          s_key[TBL];
    __shared__ int          s_prio[TBL];
    __shared__ unsigned int s_cls[TBL*3];
    __shared__ int          s_rec[TBL];
    __shared__ int          s_cnt;

    int tid = threadIdx.x;
    for (int i = tid; i < TBL; i += blockDim.x) {
        s_key[i] = -1; s_prio[i] = -1;
        s_cls[i*3] = 0u; s_cls[i*3+1] = 0u; s_cls[i*3+2] = 0u;
    }
    for (int i = tid; i < NBITW; i += blockDim.x) g_ign[i] = 0u;
    if (tid == 0) {
        s_cnt = 0;
        g_acc[0] = 0.0; g_acc[1] = 0.0; g_acc[2] = 0.0;
        g_done = 0u;
    }
    __syncthreads();

    int slot = -1, myt = -1;
    float vtx = 0.f, vty = 0.f, vtw = 0.f, vth = 0.f;

    if (tid < NGT) {
        int b = tid / TT, t = tid - b * TT;
        const float* an = annot + tid * 5;
        float a0 = an[0], a1 = an[1], a2 = an[2], a3 = an[3], a4 = an[4];
        bool valid = (a0 + a1 + a2 + a3 + a4) != 0.0f;

        float gx = a1 * (float)WW, gy = a2 * (float)HH;
        float gw = a3 * (float)WW, gh = a4 * (float)HH;
        int gi = (int)floorf(gx), gj = (int)floorf(gy);

        float ious[3];
        float best = -1.0f; int bn = 0;
        const float eps = 1e-9f;
        #pragma unroll
        for (int a = 0; a < 3; ++a) {
            float inter = fminf(gw, c_aw[a]) * fminf(gh, c_ah[a]);
            float un = gw * (gh + eps) + c_aw[a] * (c_ah[a] + eps) - inter + eps;
            float iou = inter / un;
            ious[a] = iou;
            if (iou > best) { best = iou; bn = a; }   // first max
        }

        if (gi >= 0 && gi < WW && gj >= 0 && gj < HH) {
            #pragma unroll
            for (int a = 0; a < 3; ++a) {
                bool cond = (ious[a] > IGNORE_THR) && valid;
                int ae = cond ? a : (AA - 1);         // wrap to anchor 2
                int c = ((b * AA + ae) * HH + gj) * WW + gi;
                atomicOr(&g_ign[c >> 5], 1u << (c & 31));
            }
        }

        int ii = valid ? gi : (WW - 1);               // wrap to WW-1
        if (ii >= 0 && ii < WW && gj >= 0 && gj < HH) {
            int cell = ((b * AA + bn) * HH + gj) * WW + ii;
            int j = (int)(((unsigned int)cell * 2654435761u) >> 21) & TBLM;
            while (true) {
                int old = atomicCAS(&s_key[j], -1, cell);
                if (old == -1) {
                    int r = atomicAdd(&s_cnt, 1);
                    s_rec[j] = r;
                    g_rcell[r] = cell;
                    break;
                }
                if (old == cell) break;
                j = (j + 1) & TBLM;
            }
            atomicMax(&s_prio[j], t);                 // XLA last-wins
            int ci = (int)a0;
            if (ci >= 0 && ci < NCLS)
                atomicOr(&s_cls[j*3 + (ci >> 5)], 1u << (ci & 31));
            slot = j; myt = t;
            vtx = gx - (float)gi;
            vty = gy - (float)gj;
            vtw = __logf(gw / c_aw[bn] + 1e-16f);
            vth = __logf(gh / c_ah[bn] + 1e-16f);
        }
    }
    __syncthreads();

    if (slot >= 0 && s_prio[slot] == myt) {           // unique winner writes
        int r = s_rec[slot];
        g_rtx[r] = vtx; g_rty[r] = vty; g_rtw[r] = vtw; g_rth[r] = vth;
        g_rtcls[r*3+0] = s_cls[slot*3+0];
        g_rtcls[r*3+1] = s_cls[slot*3+1];
        g_rtcls[r*3+2] = s_cls[slot*3+2];
    }
    if (tid == 0) g_npos = s_cnt;
}

// ---------------- kernel 2: fused reduce + finalize --------------------------
__global__ void __launch_bounds__(256)
k_main(const float* __restrict__ pred, float* __restrict__ out, int out_n) {
    if (blockIdx.x < DENSE_BLOCKS) {
        // sum spf(conf) over NON-ignored cells; product-of-4 -> 1 log/thread
        int tid = blockIdx.x * blockDim.x + threadIdx.x;
        double s = 0.0;
        if (tid < NV) {
            const int V_ROW = HWX / 4;                 // 1444
            int r = tid / V_ROW;
            int v = tid - r * V_ROW;
            int b = r / AA, a = r - b * AA;
            const float4 f = *reinterpret_cast<const float4*>(
                pred + (size_t)b * PRED_B + (size_t)(a * ATTR + 4) * HWX + 4 * v);
            int cbase = r * HWX + 4 * v;
            unsigned int bits = g_ign[cbase >> 5] >> (cbase & 31);
            // max per-cell factor ~ 1+e^5.6 ~ 271; product of 4 < 5.4e9, safe
            float prod = ((bits & 1u) ? 1.0f : (1.0f + __expf(f.x)))
                       * ((bits & 2u) ? 1.0f : (1.0f + __expf(f.y)))
                       * ((bits & 4u) ? 1.0f : (1.0f + __expf(f.z)))
                       * ((bits & 8u) ? 1.0f : (1.0f + __expf(f.w)));
            s = (double)__logf(prod);
        }
        blk_atomic(s, &g_acc[0]);
    } else {
        // one warp per mask record -> g_acc[1] (obj), g_acc[2] (cls)
        int widx = (blockIdx.x - DENSE_BLOCKS) * 8 + (threadIdx.x >> 5);
        int lane = threadIdx.x & 31;
        double lcls = 0.0, lobj = 0.0;

        if (widx < g_npos) {
            int cell = g_rcell[widx];
            int pix = cell % HWX;
            int ra = cell / HWX;                       // b*AA + a
            int b = ra / AA, a = ra - b * AA;
            const float* base = pred + (size_t)b * PRED_B + (size_t)(a * ATTR) * HWX;

            #pragma unroll
            for (int q = 0; q < 3; ++q) {
                int cc = lane + 32 * q;
                if (cc < NCLS) {
                    float z = base[(size_t)(5 + cc) * HWX + pix];
                    bool tgt = (g_rtcls[widx*3 + q] >> lane) & 1u;
                    lcls += (double)(tgt ? spf(-z) : spf(z));
                }
            }
            if (lane == 0) {
                float zx = base[(size_t)0 * HWX + pix];
                float zy = base[(size_t)1 * HWX + pix];
                float zw = base[(size_t)2 * HWX + pix];
                float zh = base[(size_t)3 * HWX + pix];
                float zc = base[(size_t)4 * HWX + pix];
                float tx = g_rtx[widx], ty = g_rty[widx];
                float tw = g_rtw[widx], th = g_rth[widx];
                double lxy = (double)(tx * spf(-zx) + (1.0f - tx) * spf(zx))
                           + (double)(ty * spf(-zy) + (1.0f - ty) * spf(zy));
                double lwh = (double)((zw - tw) * (zw - tw) + (zh - th) * (zh - th));
                lobj = 0.5 * lxy + 2.5 * lwh + (double)spf(-zc);
            }
        }
        blk_atomic(lcls, &g_acc[2]);
        __syncthreads();
        blk_atomic(lobj, &g_acc[1]);
    }

    // last-block finalize
    if (threadIdx.x == 0) {
        __threadfence();
        unsigned int prev = atomicAdd(&g_done, 1u);
        if (prev == (unsigned int)(TOTAL_BLOCKS - 1)) {
            const double Nd = (double)NCELL;
            double loss = (0.5 * g_acc[0] + g_acc[1]) / Nd
                        + g_acc[2] / ((double)g_npos * (double)NCLS);
            float v = (float)loss;
            for (int i = 0; i < out_n; ++i) out[i] = v;
        }
    }
}

extern "C" void kernel_launch(void* const* d_in, const int* in_sizes, int n_in,
                              void* d_out, int out_size) {
    const float* pred;
    const float* annot;
    if (n_in >= 2 && in_sizes[1] > in_sizes[0]) {
        pred  = (const float*)d_in[1];
        annot = (const float*)d_in[0];
    } else {
        pred  = (const float*)d_in[0];
        annot = (const float*)d_in[1];
    }
    k_encode<<<1, NGT>>>(annot);
    k_main<<<TOTAL_BLOCKS, 256>>>(pred, (float*)d_out, out_size);
}